// round 15
// baseline (speedup 1.0000x reference)
#include <cuda_runtime.h>
#include <cuda_fp16.h>
#include <cstdint>

// ---------------- problem constants ----------------
#define N_ROWS 16384
#define DF     128
#define KC     32                 // K per unit
#define NCHUNK 512                // units per tile
#define NTILE  128
#define NUNITS (NTILE * NCHUNK)   // 65536
#define NCTA   148
#define NSTG   6                  // ring depth (units)
#define NSLOT  3

// g_XWf: XW = x@W, fp16 pairs, fragment-plane layout per 32-k chunk (2048 u32 = 8KB).
__device__ uint32_t g_XWf[(size_t)NCHUNK * 2048];        // 4 MiB
__device__ float g_part[NSLOT][NTILE][128 * DF];         // 25.2 MiB partial numerators
__device__ float g_rs[NSLOT][NTILE][128];                // partial rowsums

__device__ __forceinline__ uint32_t packh2(float lo, float hi) {
    __half2 h = __floats2half2_rn(lo, hi);
    return *(uint32_t*)&h;
}
__device__ __forceinline__ uint32_t smem_u32(const void* p) {
    uint32_t a;
    asm("{ .reg .u64 t; cvta.to.shared.u64 t, %1; cvt.u32.u64 %0, t; }" : "=r"(a) : "l"(p));
    return a;
}
__device__ __forceinline__ void cp_async16(uint32_t dst, const void* src) {
    asm volatile("cp.async.cg.shared.global [%0], [%1], 16;" :: "r"(dst), "l"(src));
}
#define CP_COMMIT() asm volatile("cp.async.commit_group;" ::: "memory")
#define CP_WAIT(n)  asm volatile("cp.async.wait_group %0;" :: "n"(n) : "memory")

__device__ __forceinline__ void bar_sync_named(int id) {
    asm volatile("bar.sync %0, 512;" :: "r"(id) : "memory");
}
__device__ __forceinline__ void bar_arrive_named(int id) {
    asm volatile("bar.arrive %0, 512;" :: "r"(id) : "memory");
}
// ids: FULL(s)=1+s (1..6), EMPTY(s)=7+s (7..12)

// ---------------- kernel 1: XW = x @ W, emitted in fragment-plane order ----------------
#define XW_SMEM ((128 * 132 + 128 * 128) * 4)

__global__ void __launch_bounds__(256) xw_kernel(const float* __restrict__ x,
                                                 const float* __restrict__ W) {
    extern __shared__ float sm_xw[];
    float* xsT = sm_xw;              // [128][132] transposed x tile
    float* Ws  = sm_xw + 128 * 132;  // [128][128]
    uint32_t* stage = (uint32_t*)sm_xw;
    const int tid = threadIdx.x;
    const int j0 = blockIdx.x * 128;

    for (int idx = tid; idx < 128 * 128; idx += 256) {
        int j = idx >> 7, k = idx & 127;
        xsT[k * 132 + j] = x[(size_t)(j0 + j) * DF + k];
        Ws[idx] = W[idx];
    }
    __syncthreads();

    const int tx = tid & 15, ty = tid >> 4;
    const int jb = ty * 8, db = tx * 8;
    float acc[8][8];
#pragma unroll
    for (int a = 0; a < 8; a++)
#pragma unroll
        for (int b = 0; b < 8; b++) acc[a][b] = 0.0f;

    for (int k = 0; k < 128; k++) {
        float4 a0 = *(const float4*)(xsT + k * 132 + jb);
        float4 a1 = *(const float4*)(xsT + k * 132 + jb + 4);
        float4 b0 = *(const float4*)(Ws + k * 128 + db);
        float4 b1 = *(const float4*)(Ws + k * 128 + db + 4);
        float aa[8] = {a0.x, a0.y, a0.z, a0.w, a1.x, a1.y, a1.z, a1.w};
        float bb[8] = {b0.x, b0.y, b0.z, b0.w, b1.x, b1.y, b1.z, b1.w};
#pragma unroll
        for (int jj = 0; jj < 8; jj++)
#pragma unroll
            for (int dd = 0; dd < 8; dd++) acc[jj][dd] += aa[jj] * bb[dd];
    }
    __syncthreads();   // done reading xsT/Ws; reuse as staging

#pragma unroll
    for (int q = 0; q < 4; q++) {
        const int p_local = (jb >> 1) + q;
        const int c_local = p_local >> 4;
        const int kk = p_local & 15;
        const int ks = kk >> 3, r8 = kk & 7;
        const int jh = r8 >> 2, tg = r8 & 3;
#pragma unroll
        for (int dd = 0; dd < 8; dd++) {
            const int n = db + dd;
            const int h = n >> 6, ni = (n >> 3) & 7, g = n & 7;
            const int lane = 4 * g + tg;
            const int j = jh * 2 + (ni >> 2);
            const int off = c_local * 2048 + (h * 2 + ks) * 512 + j * 128
                          + lane * 4 + (ni & 3);
            stage[off] = packh2(acc[2 * q][dd], acc[2 * q + 1][dd]);
        }
    }
    __syncthreads();

    uint4* dst = (uint4*)(g_XWf + (size_t)blockIdx.x * 8192);
    const uint4* srcv = (const uint4*)stage;
#pragma unroll
    for (int i = 0; i < 8; i++) dst[tid + i * 256] = srcv[tid + i * 256];
}

// ---------------- kernel 2: balanced fused exp + softmax-GEMM over 148 CTAs --------
// unit u in [0, 65536): tile = u>>9, chunk = u&511. CTA bx handles a contiguous range.
// Ring: 6 stages x { A: 128x20 u32 (10240B), B: 2048 u32 (8192B) } = 110592B.
#define SA2 20
#define A_STG_B  (128 * SA2 * 4)                 // 10240
#define B_STG_B  8192
#define A_OFF    0u
#define B_OFF    (A_OFF + NSTG * A_STG_B)        // 61440
#define FUSED_SMEM (B_OFF + NSTG * B_STG_B)      // 110592

__global__ void __launch_bounds__(512, 1) fused_kernel(const float* __restrict__ adj) {
    extern __shared__ char sm8[];
    const uint32_t sb = smem_u32(sm8);

    const int bx = blockIdx.x;
    const int tid = threadIdx.x;
    const int u0 = (bx * NUNITS) / NCTA;
    const int u1 = ((bx + 1) * NUNITS) / NCTA;
    const int nU = u1 - u0;
    const int slot = bx % NSLOT;

    if (tid >= 256) {
        // ================= PRODUCERS =================
        const int ptid = tid - 256;
        const int r = ptid >> 1;           // adj row within tile
        const int hf = ptid & 1;           // 16-float half of 32-col chunk
        const uint32_t a_sts = (uint32_t)r * SA2 + hf * 8;

        const uint32_t* bgsrc = g_XWf + (size_t)ptid * 8;
        const uint32_t b_dst = sb + B_OFF + (uint32_t)ptid * 32;

        float4 a0b[4], a1b[4];
        float rsum = 0.0f;

#define ADJP(u) (adj + (size_t)(((u) >> 9) * 128 + r) * N_ROWS \
                     + (size_t)((u) & 511) * KC + hf * 16)
#define LDGA(u, BUF) do {                                                        \
            const float* _p = ADJP(u);                                           \
            BUF[0] = *(const float4*)(_p);                                       \
            BUF[1] = *(const float4*)(_p + 4);                                   \
            BUF[2] = *(const float4*)(_p + 8);                                   \
            BUF[3] = *(const float4*)(_p + 12);                                  \
        } while (0)
#define CPB(u, S) do {                                                           \
            const uint32_t* _p = bgsrc + (size_t)((u) & 511) * 2048;             \
            uint32_t _d = b_dst + (uint32_t)(S) * B_STG_B;                       \
            cp_async16(_d,      _p);                                             \
            cp_async16(_d + 16, _p + 4);                                         \
            CP_COMMIT();                                                         \
        } while (0)
#define STSA(BUF, S) do {                                                        \
            uint32_t pk[8];                                                      \
            _Pragma("unroll")                                                    \
            for (int q = 0; q < 4; q++) {                                        \
                float e0 = __expf(BUF[q].x), e1 = __expf(BUF[q].y);              \
                float e2 = __expf(BUF[q].z), e3 = __expf(BUF[q].w);              \
                rsum += (e0 + e1) + (e2 + e3);                                   \
                pk[2 * q]     = packh2(e0, e1);                                  \
                pk[2 * q + 1] = packh2(e2, e3);                                  \
            }                                                                    \
            uint32_t* As = (uint32_t*)(sm8 + A_OFF + (size_t)(S) * A_STG_B);     \
            *(uint4*)(As + a_sts)     = make_uint4(pk[0], pk[1], pk[2], pk[3]);  \
            *(uint4*)(As + a_sts + 4) = make_uint4(pk[4], pk[5], pk[6], pk[7]);  \
        } while (0)

        LDGA(u0, a0b);
        if (nU > 1) LDGA(u0 + 1, a1b);
        CPB(u0, 0);
        if (nU > 1) CPB(u0 + 1, 1);

        int s = 0;
        for (int i = 0; i < nU; ++i) {
            const int u = u0 + i;
            // issue B two units ahead into stage s+2 (guard with EMPTY if reused)
            if (i + 2 < nU) {
                const int s2 = (s >= 4) ? s - 4 : s + 2;
                if (i + 2 >= NSTG) bar_sync_named(7 + s2);
                CPB(u + 2, s2);
            }
            // exp + STS A of unit i (stage s was EMPTY-synced when CPB(i) was issued)
            if (i & 1) STSA(a1b, s); else STSA(a0b, s);
            // prefetch adj for unit i+2 into the buffer just consumed
            if (i + 2 < nU) { if (i & 1) LDGA(u + 2, a1b); else LDGA(u + 2, a0b); }
            // ensure B group of unit i has landed (<=2 newer groups outstanding)
            if (i + 2 < nU) { CP_WAIT(2); }
            else if (i + 1 < nU) { CP_WAIT(1); }
            else { CP_WAIT(0); }
            __threadfence_block();
            bar_arrive_named(1 + s);

            // rowsum flush at tile end / range end
            if (i == nU - 1 || ((u + 1) & 511) == 0) {
                float tot = rsum + __shfl_xor_sync(0xffffffffu, rsum, 1);
                if (hf == 0) g_rs[slot][u >> 9][r] = tot;
                rsum = 0.0f;
            }
            s = (s == NSTG - 1) ? 0 : s + 1;
        }
    } else {
        // ================= CONSUMERS =================
        const int wid = tid >> 5;
        const int lid = tid & 31;
        const int g = lid >> 2, tg = lid & 3;
        const int mB = (wid & 3) * 32;
        const int h  = wid >> 2;
        const int nB = h * 64;

        float acc[2][8][4];
#pragma unroll
        for (int i = 0; i < 2; i++)
#pragma unroll
            for (int j = 0; j < 8; j++)
#pragma unroll
                for (int c = 0; c < 4; c++) acc[i][j][c] = 0.0f;

        int s = 0;
        for (int i = 0; i < nU; ++i) {
            bar_sync_named(1 + s);
            const uint32_t* As = (const uint32_t*)(sm8 + A_OFF + (size_t)s * A_STG_B);
            const uint32_t* Bs = (const uint32_t*)(sm8 + B_OFF + (size_t)s * B_STG_B);
#pragma unroll
            for (int ks = 0; ks < 2; ks++) {
                uint32_t af[2][4];
#pragma unroll
                for (int mi = 0; mi < 2; mi++) {
                    const uint32_t* Ar = As + (mB + mi * 16 + g) * SA2 + ks * 8 + tg;
                    af[mi][0] = Ar[0];
                    af[mi][1] = Ar[8 * SA2];
                    af[mi][2] = Ar[4];
                    af[mi][3] = Ar[8 * SA2 + 4];
                }
                const uint32_t* Bb = Bs + (h * 2 + ks) * 512 + lid * 4;
                const uint4 q0 = *(const uint4*)(Bb);
                const uint4 q1 = *(const uint4*)(Bb + 128);
                const uint4 q2 = *(const uint4*)(Bb + 256);
                const uint4 q3 = *(const uint4*)(Bb + 384);
                const uint32_t b0a[8] = {q0.x, q0.y, q0.z, q0.w, q1.x, q1.y, q1.z, q1.w};
                const uint32_t b1a[8] = {q2.x, q2.y, q2.z, q2.w, q3.x, q3.y, q3.z, q3.w};
#pragma unroll
                for (int ni = 0; ni < 8; ni++) {
#pragma unroll
                    for (int mi = 0; mi < 2; mi++) {
                        asm volatile(
                            "mma.sync.aligned.m16n8k16.row.col.f32.f16.f16.f32 "
                            "{%0,%1,%2,%3}, {%4,%5,%6,%7}, {%8,%9}, {%0,%1,%2,%3};"
                            : "+f"(acc[mi][ni][0]), "+f"(acc[mi][ni][1]),
                              "+f"(acc[mi][ni][2]), "+f"(acc[mi][ni][3])
                            : "r"(af[mi][0]), "r"(af[mi][1]), "r"(af[mi][2]), "r"(af[mi][3]),
                              "r"(b0a[ni]), "r"(b1a[ni]));
                    }
                }
            }
            bar_arrive_named(7 + s);

            // flush raw accumulators at tile end / range end
            const int u = u0 + i;
            if (i == nU - 1 || ((u + 1) & 511) == 0) {
                float* base = g_part[slot][u >> 9];
#pragma unroll
                for (int mi = 0; mi < 2; mi++) {
                    const int r0 = mB + mi * 16 + g;
                    const int r1 = r0 + 8;
#pragma unroll
                    for (int ni = 0; ni < 8; ni++) {
                        const int c = nB + ni * 8 + 2 * tg;
                        *(float2*)(base + r0 * DF + c) =
                            make_float2(acc[mi][ni][0], acc[mi][ni][1]);
                        *(float2*)(base + r1 * DF + c) =
                            make_float2(acc[mi][ni][2], acc[mi][ni][3]);
                        acc[mi][ni][0] = acc[mi][ni][1] = 0.0f;
                        acc[mi][ni][2] = acc[mi][ni][3] = 0.0f;
                    }
                }
            }
            s = (s == NSTG - 1) ? 0 : s + 1;
        }
    }
}

// ---------------- kernel 3: combine partials, divide, bias ----------------
__global__ void __launch_bounds__(256) combine_kernel(const float* __restrict__ bias,
                                                      float* __restrict__ out) {
    __shared__ float inv_sm[128];
    __shared__ float b_sm[DF];
    const int t = blockIdx.x;
    const int tid = threadIdx.x;
    if (tid < 128) {
        float d = g_rs[0][t][tid] + g_rs[1][t][tid] + g_rs[2][t][tid];
        inv_sm[tid] = 1.0f / d;
        b_sm[tid] = bias[tid];
    }
    __syncthreads();

    const float4* p0 = (const float4*)g_part[0][t];
    const float4* p1 = (const float4*)g_part[1][t];
    const float4* p2 = (const float4*)g_part[2][t];
    float4* o = (float4*)(out + (size_t)t * 128 * DF);

    for (int i = tid; i < 128 * DF / 4; i += 256) {
        const int r = i >> 5;            // 32 float4 per row
        const int c = (i & 31) * 4;
        const float inv = inv_sm[r];
        float4 a = p0[i], b = p1[i], c4 = p2[i];
        float4 v;
        v.x = (a.x + b.x + c4.x) * inv + b_sm[c];
        v.y = (a.y + b.y + c4.y) * inv + b_sm[c + 1];
        v.z = (a.z + b.z + c4.z) * inv + b_sm[c + 2];
        v.w = (a.w + b.w + c4.w) * inv + b_sm[c + 3];
        o[i] = v;
    }
}

// ---------------- launcher ----------------
extern "C" void kernel_launch(void* const* d_in, const int* in_sizes, int n_in,
                              void* d_out, int out_size) {
    const float* x   = (const float*)d_in[0];
    const float* adj = (const float*)d_in[1];
    const float* W   = (const float*)d_in[2];
    const float* b   = (const float*)d_in[3];
    float* out = (float*)d_out;
    (void)in_sizes; (void)n_in; (void)out_size;

    cudaFuncSetAttribute(xw_kernel, cudaFuncAttributeMaxDynamicSharedMemorySize, XW_SMEM);
    cudaFuncSetAttribute(fused_kernel, cudaFuncAttributeMaxDynamicSharedMemorySize, FUSED_SMEM);

    xw_kernel<<<N_ROWS / 128, 256, XW_SMEM>>>(x, W);
    fused_kernel<<<NCTA, 512, FUSED_SMEM>>>(adj);
    combine_kernel<<<NTILE, 256>>>(b, out);
}

// round 16
// speedup vs baseline: 1.6642x; 1.6642x over previous
#include <cuda_runtime.h>
#include <cuda_fp16.h>
#include <cstdint>

// ---------------- problem constants ----------------
#define N_ROWS 16384
#define DF     128
#define KC     32                 // K per unit (chunk)
#define NCHUNK 512                // chunks per tile
#define NTILE  128
#define NPAIRS_TOT (NTILE * NCHUNK / 2)   // 32768 pairs
#define NCTA   148
#define NPAIR  3                  // ring = 3 pairs = 6 stages
#define NSLOT  3

// g_XWf: XW = x@W, fp16 pairs, fragment-plane layout per 32-k chunk (2048 u32 = 8KB).
__device__ uint32_t g_XWf[(size_t)NCHUNK * 2048];        // 4 MiB
__device__ float g_part[NSLOT][NTILE][128 * DF];         // partial numerators (zero-init)
__device__ float g_rs[NSLOT][NTILE][128];                // partial rowsums   (zero-init)

__device__ __forceinline__ uint32_t packh2(float lo, float hi) {
    __half2 h = __floats2half2_rn(lo, hi);
    return *(uint32_t*)&h;
}
__device__ __forceinline__ uint32_t smem_u32(const void* p) {
    uint32_t a;
    asm("{ .reg .u64 t; cvta.to.shared.u64 t, %1; cvt.u32.u64 %0, t; }" : "=r"(a) : "l"(p));
    return a;
}
__device__ __forceinline__ void cp_async16(uint32_t dst, const void* src) {
    asm volatile("cp.async.cg.shared.global [%0], [%1], 16;" :: "r"(dst), "l"(src));
}
#define CP_COMMIT() asm volatile("cp.async.commit_group;" ::: "memory")
#define CP_WAIT(n)  asm volatile("cp.async.wait_group %0;" :: "n"(n) : "memory")

__device__ __forceinline__ void bar_sync_named(int id) {
    asm volatile("bar.sync %0, 512;" :: "r"(id) : "memory");
}
__device__ __forceinline__ void bar_arrive_named(int id) {
    asm volatile("bar.arrive %0, 512;" :: "r"(id) : "memory");
}
// barrier ids: FULL(p)=1+p (1..3), EMPTY(p)=4+p (4..6)

// ---------------- kernel 1: XW = x @ W, emitted in fragment-plane order ----------------
#define XW_SMEM ((128 * 132 + 128 * 128) * 4)

__global__ void __launch_bounds__(256) xw_kernel(const float* __restrict__ x,
                                                 const float* __restrict__ W) {
    extern __shared__ float sm_xw[];
    float* xsT = sm_xw;              // [128][132] transposed x tile
    float* Ws  = sm_xw + 128 * 132;  // [128][128]
    uint32_t* stage = (uint32_t*)sm_xw;
    const int tid = threadIdx.x;
    const int j0 = blockIdx.x * 128;

    for (int idx = tid; idx < 128 * 128; idx += 256) {
        int j = idx >> 7, k = idx & 127;
        xsT[k * 132 + j] = x[(size_t)(j0 + j) * DF + k];
        Ws[idx] = W[idx];
    }
    __syncthreads();

    const int tx = tid & 15, ty = tid >> 4;
    const int jb = ty * 8, db = tx * 8;
    float acc[8][8];
#pragma unroll
    for (int a = 0; a < 8; a++)
#pragma unroll
        for (int b = 0; b < 8; b++) acc[a][b] = 0.0f;

    for (int k = 0; k < 128; k++) {
        float4 a0 = *(const float4*)(xsT + k * 132 + jb);
        float4 a1 = *(const float4*)(xsT + k * 132 + jb + 4);
        float4 b0 = *(const float4*)(Ws + k * 128 + db);
        float4 b1 = *(const float4*)(Ws + k * 128 + db + 4);
        float aa[8] = {a0.x, a0.y, a0.z, a0.w, a1.x, a1.y, a1.z, a1.w};
        float bb[8] = {b0.x, b0.y, b0.z, b0.w, b1.x, b1.y, b1.z, b1.w};
#pragma unroll
        for (int jj = 0; jj < 8; jj++)
#pragma unroll
            for (int dd = 0; dd < 8; dd++) acc[jj][dd] += aa[jj] * bb[dd];
    }
    __syncthreads();   // done reading xsT/Ws; reuse as staging

#pragma unroll
    for (int q = 0; q < 4; q++) {
        const int p_local = (jb >> 1) + q;
        const int c_local = p_local >> 4;
        const int kk = p_local & 15;
        const int ks = kk >> 3, r8 = kk & 7;
        const int jh = r8 >> 2, tg = r8 & 3;
#pragma unroll
        for (int dd = 0; dd < 8; dd++) {
            const int n = db + dd;
            const int h = n >> 6, ni = (n >> 3) & 7, g = n & 7;
            const int lane = 4 * g + tg;
            const int j = jh * 2 + (ni >> 2);
            const int off = c_local * 2048 + (h * 2 + ks) * 512 + j * 128
                          + lane * 4 + (ni & 3);
            stage[off] = packh2(acc[2 * q][dd], acc[2 * q + 1][dd]);
        }
    }
    __syncthreads();

    uint4* dst = (uint4*)(g_XWf + (size_t)blockIdx.x * 8192);
    const uint4* srcv = (const uint4*)stage;
#pragma unroll
    for (int i = 0; i < 8; i++) dst[tid + i * 256] = srcv[tid + i * 256];
}

// ---------------- kernel 2: balanced K-split fused kernel (pair granularity) ---------
// pair q in [0, 32768): tile = q>>8, chunks (2q, 2q+1). CTA bx handles pairs [q0, q1).
// Ring: 3 pairs = 6 stages x { A: 128x20 u32 (10240B), B: 2048 u32 (8192B) }.
#define SA2 20
#define A_STG_B  (128 * SA2 * 4)                 // 10240
#define B_STG_B  8192
#define A_OFF    0u
#define B_OFF    (A_OFF + 6 * A_STG_B)           // 61440
#define FUSED_SMEM (B_OFF + 6 * B_STG_B)         // 110592

__global__ void __launch_bounds__(512, 1) fused_kernel(const float* __restrict__ adj) {
    extern __shared__ char sm8[];
    const uint32_t sb = smem_u32(sm8);

    const int bx = blockIdx.x;
    const int tid = threadIdx.x;
    const int q0 = (int)(((long long)bx * NPAIRS_TOT) / NCTA);
    const int q1 = (int)(((long long)(bx + 1) * NPAIRS_TOT) / NCTA);
    const int nP = q1 - q0;
    const int slot = bx % NSLOT;

    if (tid >= 256) {
        // ================= PRODUCERS =================
        const int ptid = tid - 256;
        const int r = ptid >> 1;           // adj row within tile
        const int hf = ptid & 1;           // 16-float half of 32-col chunk
        const uint32_t a_sts = (uint32_t)r * SA2 + hf * 8;   // u32 units

        const uint32_t* bgsrc = g_XWf + (size_t)ptid * 8;
        const uint32_t b_dst = sb + B_OFF + (uint32_t)ptid * 32;

        float4 a0b[4], a1b[4];
        float rsum = 0.0f;

#define ADJP(u) (adj + (size_t)(((u) >> 9) * 128 + r) * N_ROWS \
                     + (size_t)((u) & 511) * KC + hf * 16)
#define LDGA(u, BUF) do {                                                        \
            const float* _p = ADJP(u);                                           \
            BUF[0] = *(const float4*)(_p);                                       \
            BUF[1] = *(const float4*)(_p + 4);                                   \
            BUF[2] = *(const float4*)(_p + 8);                                   \
            BUF[3] = *(const float4*)(_p + 12);                                  \
        } while (0)
#define CPB(u, S) do {                                                           \
            const uint32_t* _p = bgsrc + (size_t)((u) & 511) * 2048;             \
            uint32_t _d = b_dst + (uint32_t)(S) * B_STG_B;                       \
            cp_async16(_d,      _p);                                             \
            cp_async16(_d + 16, _p + 4);                                         \
        } while (0)
#define STSA(BUF, S) do {                                                        \
            uint32_t pk[8];                                                      \
            _Pragma("unroll")                                                    \
            for (int qq = 0; qq < 4; qq++) {                                     \
                float e0 = __expf(BUF[qq].x), e1 = __expf(BUF[qq].y);            \
                float e2 = __expf(BUF[qq].z), e3 = __expf(BUF[qq].w);            \
                rsum += (e0 + e1) + (e2 + e3);                                   \
                pk[2 * qq]     = packh2(e0, e1);                                 \
                pk[2 * qq + 1] = packh2(e2, e3);                                 \
            }                                                                    \
            uint32_t* As = (uint32_t*)(sm8 + A_OFF + (size_t)(S) * A_STG_B);     \
            *(uint4*)(As + a_sts)     = make_uint4(pk[0], pk[1], pk[2], pk[3]);  \
            *(uint4*)(As + a_sts + 4) = make_uint4(pk[4], pk[5], pk[6], pk[7]);  \
        } while (0)

        LDGA(2 * q0, a0b);
        LDGA(2 * q0 + 1, a1b);
        // prologue: B for pair q0 into ring pair 0 (one commit group)
        CPB(2 * q0, 0);
        CPB(2 * q0 + 1, 1);
        CP_COMMIT();

        int p = 0;
        for (int j = 0; j < nP; ++j) {
            const int q = q0 + j;
            const int pn = (p == NPAIR - 1) ? 0 : p + 1;
            // issue B for NEXT pair (one pair ahead) into ring pn
            if (j + 1 < nP) {
                if (j + 1 >= NPAIR) bar_sync_named(4 + pn);   // slots 2pn,2pn+1 free
                CPB(2 * (q + 1), 2 * pn);
                CPB(2 * (q + 1) + 1, 2 * pn + 1);
                CP_COMMIT();
            }
            // exp + STS this pair's A; prefetch next pair's adj
            STSA(a0b, 2 * p);
            if (j + 1 < nP) LDGA(2 * (q + 1), a0b);
            STSA(a1b, 2 * p + 1);
            if (j + 1 < nP) LDGA(2 * (q + 1) + 1, a1b);
            // B of THIS pair must be complete; next pair still in flight
            if (j + 1 < nP) { CP_WAIT(1); } else { CP_WAIT(0); }
            __threadfence_block();
            bar_arrive_named(1 + p);

            // rowsum flush at tile end / range end
            if (j == nP - 1 || ((q + 1) & 255) == 0) {
                float tot = rsum + __shfl_xor_sync(0xffffffffu, rsum, 1);
                if (hf == 0) g_rs[slot][q >> 8][r] = tot;
                rsum = 0.0f;
            }
            p = pn;
        }
    } else {
        // ================= CONSUMERS =================
        const int wid = tid >> 5;
        const int lid = tid & 31;
        const int g = lid >> 2, tg = lid & 3;
        const int mB = (wid & 3) * 32;
        const int h  = wid >> 2;
        const int nB = h * 64;

        float acc[2][8][4];
#pragma unroll
        for (int i = 0; i < 2; i++)
#pragma unroll
            for (int j = 0; j < 8; j++)
#pragma unroll
                for (int c = 0; c < 4; c++) acc[i][j][c] = 0.0f;

        int p = 0;
        for (int j = 0; j < nP; ++j) {
            bar_sync_named(1 + p);
#pragma unroll
            for (int half = 0; half < 2; half++) {
                const int s = 2 * p + half;
                const uint32_t* As = (const uint32_t*)(sm8 + A_OFF + (size_t)s * A_STG_B);
                const uint32_t* Bs = (const uint32_t*)(sm8 + B_OFF + (size_t)s * B_STG_B);
#pragma unroll
                for (int ks = 0; ks < 2; ks++) {
                    uint32_t af[2][4];
#pragma unroll
                    for (int mi = 0; mi < 2; mi++) {
                        const uint32_t* Ar = As + (mB + mi * 16 + g) * SA2 + ks * 8 + tg;
                        af[mi][0] = Ar[0];
                        af[mi][1] = Ar[8 * SA2];
                        af[mi][2] = Ar[4];
                        af[mi][3] = Ar[8 * SA2 + 4];
                    }
                    const uint32_t* Bb = Bs + (h * 2 + ks) * 512 + lid * 4;
                    const uint4 v0 = *(const uint4*)(Bb);
                    const uint4 v1 = *(const uint4*)(Bb + 128);
                    const uint4 v2 = *(const uint4*)(Bb + 256);
                    const uint4 v3 = *(const uint4*)(Bb + 384);
                    const uint32_t b0a[8] = {v0.x, v0.y, v0.z, v0.w, v1.x, v1.y, v1.z, v1.w};
                    const uint32_t b1a[8] = {v2.x, v2.y, v2.z, v2.w, v3.x, v3.y, v3.z, v3.w};
#pragma unroll
                    for (int ni = 0; ni < 8; ni++) {
#pragma unroll
                        for (int mi = 0; mi < 2; mi++) {
                            asm volatile(
                                "mma.sync.aligned.m16n8k16.row.col.f32.f16.f16.f32 "
                                "{%0,%1,%2,%3}, {%4,%5,%6,%7}, {%8,%9}, {%0,%1,%2,%3};"
                                : "+f"(acc[mi][ni][0]), "+f"(acc[mi][ni][1]),
                                  "+f"(acc[mi][ni][2]), "+f"(acc[mi][ni][3])
                                : "r"(af[mi][0]), "r"(af[mi][1]), "r"(af[mi][2]), "r"(af[mi][3]),
                                  "r"(b0a[ni]), "r"(b1a[ni]));
                        }
                    }
                }
            }
            bar_arrive_named(4 + p);

            // flush raw accumulators at tile end / range end
            const int q = q0 + j;
            if (j == nP - 1 || ((q + 1) & 255) == 0) {
                float* base = g_part[slot][q >> 8];
#pragma unroll
                for (int mi = 0; mi < 2; mi++) {
                    const int r0 = mB + mi * 16 + g;
                    const int r1 = r0 + 8;
#pragma unroll
                    for (int ni = 0; ni < 8; ni++) {
                        const int c = nB + ni * 8 + 2 * tg;
                        *(float2*)(base + r0 * DF + c) =
                            make_float2(acc[mi][ni][0], acc[mi][ni][1]);
                        *(float2*)(base + r1 * DF + c) =
                            make_float2(acc[mi][ni][2], acc[mi][ni][3]);
                        acc[mi][ni][0] = acc[mi][ni][1] = 0.0f;
                        acc[mi][ni][2] = acc[mi][ni][3] = 0.0f;
                    }
                }
            }
            p = (p == NPAIR - 1) ? 0 : p + 1;
        }
    }
}

// ---------------- kernel 3: combine partials, divide, bias ----------------
__global__ void __launch_bounds__(256) combine_kernel(const float* __restrict__ bias,
                                                      float* __restrict__ out) {
    __shared__ float inv_sm[128];
    __shared__ float b_sm[DF];
    const int t = blockIdx.x;
    const int tid = threadIdx.x;
    if (tid < 128) {
        float d = g_rs[0][t][tid] + g_rs[1][t][tid] + g_rs[2][t][tid];
        inv_sm[tid] = 1.0f / d;
        b_sm[tid] = bias[tid];
    }
    __syncthreads();

    const float4* p0 = (const float4*)g_part[0][t];
    const float4* p1 = (const float4*)g_part[1][t];
    const float4* p2 = (const float4*)g_part[2][t];
    float4* o = (float4*)(out + (size_t)t * 128 * DF);

    for (int i = tid; i < 128 * DF / 4; i += 256) {
        const int r = i >> 5;            // 32 float4 per row
        const int c = (i & 31) * 4;
        const float inv = inv_sm[r];
        float4 a = p0[i], b = p1[i], c4 = p2[i];
        float4 v;
        v.x = (a.x + b.x + c4.x) * inv + b_sm[c];
        v.y = (a.y + b.y + c4.y) * inv + b_sm[c + 1];
        v.z = (a.z + b.z + c4.z) * inv + b_sm[c + 2];
        v.w = (a.w + b.w + c4.w) * inv + b_sm[c + 3];
        o[i] = v;
    }
}

// ---------------- launcher ----------------
extern "C" void kernel_launch(void* const* d_in, const int* in_sizes, int n_in,
                              void* d_out, int out_size) {
    const float* x   = (const float*)d_in[0];
    const float* adj = (const float*)d_in[1];
    const float* W   = (const float*)d_in[2];
    const float* b   = (const float*)d_in[3];
    float* out = (float*)d_out;
    (void)in_sizes; (void)n_in; (void)out_size;

    cudaFuncSetAttribute(xw_kernel, cudaFuncAttributeMaxDynamicSharedMemorySize, XW_SMEM);
    cudaFuncSetAttribute(fused_kernel, cudaFuncAttributeMaxDynamicSharedMemorySize, FUSED_SMEM);

    xw_kernel<<<N_ROWS / 128, 256, XW_SMEM>>>(x, W);
    fused_kernel<<<NCTA, 512, FUSED_SMEM>>>(adj);
    combine_kernel<<<NTILE, 256>>>(b, out);
}